// round 10
// baseline (speedup 1.0000x reference)
#include <cuda_runtime.h>
#include <stdint.h>

#define M_DIM 2048   // 8*256
#define N_DIM 1024   // out_features
#define K_DIM 1024   // in_features
#define KHALF 512

// Scratch (device globals; no allocation allowed)
__device__ float g_xf[K_DIM * M_DIM];  // decoded x, K-major: xf_t[k][m]
__device__ float g_wf[K_DIM * N_DIM];  // decoded w, K-major: wf_t[k][n]
__device__ float g_y0[M_DIM * N_DIM];  // s0 = chain k in [0,512)
__device__ float g_y1[M_DIM * N_DIM];  // s1 = chain k in [512,1024)

// ---------------------------------------------------------------------------
// Decode FP8-E4M3 bit pulses -> fp32 (exact), writing K-major transposed.
// ---------------------------------------------------------------------------
__device__ __forceinline__ float decode_one(const float4* p)
{
    float4 a = p[0];
    float4 b = p[1];
    int s  = a.x > 0.5f;
    int ev = ((a.y > 0.5f) << 3) | ((a.z > 0.5f) << 2) |
             ((a.w > 0.5f) << 1) |  (b.x > 0.5f);
    int mv = ((b.y > 0.5f) << 2) | ((b.z > 0.5f) << 1) | (b.w > 0.5f);
    float frac = (float)mv * 0.125f;
    float mag;
    if (ev == 0) {
        mag = frac * 0.015625f;                     // frac * 2^-6 (exact)
    } else {
        float scale = __uint_as_float((unsigned)(ev + 120) << 23);  // 2^(ev-7)
        mag = (1.0f + frac) * scale;                // exact
    }
    return s ? -mag : mag;
}

__global__ void __launch_bounds__(256) decode_t_kernel(
    const float4* __restrict__ p, float* __restrict__ out, int rows)
{
    __shared__ float tile[32][33];
    const int m0 = blockIdx.y * 32;
    const int k0 = blockIdx.x * 32;
    const int t  = threadIdx.x;

#pragma unroll
    for (int r = 0; r < 4; r++) {
        int lin = t + r * 256;          // m-major
        int mm  = lin >> 5;
        int kk  = lin & 31;
        tile[kk][mm] = decode_one(p + 2 * ((size_t)(m0 + mm) * K_DIM + k0 + kk));
    }
    __syncthreads();
#pragma unroll
    for (int r = 0; r < 4; r++) {
        int lin = t + r * 256;          // k-major
        int kk  = lin >> 5;
        int mm  = lin & 31;
        out[(size_t)(k0 + kk) * rows + m0 + mm] = tile[kk][mm];
    }
}

// ---------------------------------------------------------------------------
// fp32 GEMM, split-K=2 reference order; blockIdx.z selects K half.
// Packed fma.rn.f32x2 (FFMA2): two independent IEEE-RN fmas per issue ->
// bit-identical per-element ascending-k chains, half the FMA issue slots.
// 128x128 tile, BK=16, 256 threads, 8x8 micro-tile, 3-stage cp.async.
// ---------------------------------------------------------------------------
#define BM 128
#define BN 128
#define BK 16
#define NHT (KHALF / BK)   // 32 tiles per half
#define PAD 4
#define SROW (BM + PAD)    // 132 floats (528B rows, 16B aligned)
#define STAGES 3

#define CP_ASYNC16(dst_u32, src_ptr) \
    asm volatile("cp.async.cg.shared.global [%0], [%1], 16;" \
                 :: "r"(dst_u32), "l"(src_ptr))
#define CP_COMMIT() asm volatile("cp.async.commit_group;")
#define CP_WAIT(n)  asm volatile("cp.async.wait_group %0;" :: "n"(n))

__device__ __forceinline__ uint32_t smem_u32(const void* p) {
    uint32_t a;
    asm("{ .reg .u64 t; cvta.to.shared.u64 t, %1; cvt.u32.u64 %0, t; }"
        : "=r"(a) : "l"(p));
    return a;
}

__device__ __forceinline__ void fma2(unsigned long long& d,
                                     unsigned long long a,
                                     unsigned long long b) {
    asm("fma.rn.f32x2 %0, %1, %2, %0;" : "+l"(d) : "l"(a), "l"(b));
}
__device__ __forceinline__ unsigned long long dup2(float v) {
    unsigned long long r;
    unsigned u = __float_as_uint(v);
    asm("mov.b64 %0, {%1, %1};" : "=l"(r) : "r"(u));
    return r;
}
__device__ __forceinline__ float2 unpack2(unsigned long long v) {
    unsigned lo, hi;
    asm("mov.b64 {%0, %1}, %2;" : "=r"(lo), "=r"(hi) : "l"(v));
    return make_float2(__uint_as_float(lo), __uint_as_float(hi));
}

__global__ void __launch_bounds__(256, 2) gemm_kernel()
{
    __shared__ float As[STAGES][BK][SROW];
    __shared__ float Bs[STAGES][BK][SROW];

    const int tid = threadIdx.x;
    const int tx  = tid & 15;
    const int ty  = tid >> 4;
    const int m0  = blockIdx.y * BM;
    const int n0  = blockIdx.x * BN;
    const int KOFF = blockIdx.z * KHALF;
    float* yout = blockIdx.z ? g_y1 : g_y0;

    const int kkA = tid >> 5,         posA = tid & 31;
    const int kkB = (tid + 256) >> 5, posB = (tid + 256) & 31;
    const float* Asrc0 = &g_xf[(size_t)(KOFF + kkA) * M_DIM + m0 + posA * 4];
    const float* Asrc1 = &g_xf[(size_t)(KOFF + kkB) * M_DIM + m0 + posB * 4];
    const float* Bsrc0 = &g_wf[(size_t)(KOFF + kkA) * N_DIM + n0 + posA * 4];
    const float* Bsrc1 = &g_wf[(size_t)(KOFF + kkB) * N_DIM + n0 + posB * 4];
    const size_t stepA = (size_t)BK * M_DIM;
    const size_t stepB = (size_t)BK * N_DIM;

    uint32_t dA0[STAGES], dA1[STAGES], dB0[STAGES], dB1[STAGES];
#pragma unroll
    for (int b = 0; b < STAGES; b++) {
        dA0[b] = smem_u32(&As[b][kkA][posA * 4]);
        dA1[b] = smem_u32(&As[b][kkB][posB * 4]);
        dB0[b] = smem_u32(&Bs[b][kkA][posA * 4]);
        dB1[b] = smem_u32(&Bs[b][kkB][posB * 4]);
    }

    unsigned long long acc[8][4];   // [mi][nj-pair], packed f32x2
#pragma unroll
    for (int i = 0; i < 8; i++)
#pragma unroll
        for (int j = 0; j < 4; j++) acc[i][j] = 0ULL;

    // prologue: issue tiles 0 and 1
#pragma unroll
    for (int pt = 0; pt < 2; pt++) {
        const size_t oA = (size_t)pt * stepA;
        const size_t oB = (size_t)pt * stepB;
        CP_ASYNC16(dA0[pt], Asrc0 + oA);
        CP_ASYNC16(dA1[pt], Asrc1 + oA);
        CP_ASYNC16(dB0[pt], Bsrc0 + oB);
        CP_ASYNC16(dB1[pt], Bsrc1 + oB);
        CP_COMMIT();
    }

    for (int kt = 0; kt < NHT; kt++) {
        const int buf = kt % STAGES;
        if (kt < NHT - 1) CP_WAIT(1); else CP_WAIT(0);
        __syncthreads();

        // issue tile kt+2 (overlaps with compute of tile kt)
        if (kt + 2 < NHT) {
            const int nb = (kt + 2) % STAGES;
            const size_t oA = (size_t)(kt + 2) * stepA;
            const size_t oB = (size_t)(kt + 2) * stepB;
            CP_ASYNC16(dA0[nb], Asrc0 + oA);
            CP_ASYNC16(dA1[nb], Asrc1 + oA);
            CP_ASYNC16(dB0[nb], Bsrc0 + oB);
            CP_ASYNC16(dB1[nb], Bsrc1 + oB);
            CP_COMMIT();
        }

#pragma unroll
        for (int kk = 0; kk < BK; kk++) {
            float4 a0 = *(const float4*)&As[buf][kk][ty * 8];
            float4 a1 = *(const float4*)&As[buf][kk][ty * 8 + 4];
            const ulonglong2* bp = (const ulonglong2*)&Bs[buf][kk][tx * 8];
            ulonglong2 bq0 = bp[0];           // (b0,b1),(b2,b3)
            ulonglong2 bq1 = bp[1];           // (b4,b5),(b6,b7)
            unsigned long long bv[4] = {bq0.x, bq0.y, bq1.x, bq1.y};
            unsigned long long av[8];
            av[0] = dup2(a0.x); av[1] = dup2(a0.y);
            av[2] = dup2(a0.z); av[3] = dup2(a0.w);
            av[4] = dup2(a1.x); av[5] = dup2(a1.y);
            av[6] = dup2(a1.z); av[7] = dup2(a1.w);
#pragma unroll
            for (int i = 0; i < 8; i++)
#pragma unroll
                for (int j = 0; j < 4; j++)
                    fma2(acc[i][j], av[i], bv[j]);
        }
        __syncthreads();
    }

#pragma unroll
    for (int i = 0; i < 8; i++) {
        size_t base = (size_t)(m0 + ty * 8 + i) * N_DIM + n0 + tx * 8;
        float2 p0 = unpack2(acc[i][0]);
        float2 p1 = unpack2(acc[i][1]);
        float2 p2 = unpack2(acc[i][2]);
        float2 p3 = unpack2(acc[i][3]);
        *(float4*)&yout[base]     = make_float4(p0.x, p0.y, p1.x, p1.y);
        *(float4*)&yout[base + 4] = make_float4(p2.x, p2.y, p3.x, p3.y);
    }
}

// ---------------------------------------------------------------------------
// Encode (s0 + s1) -> 32 bit pulses (MSB first). One thread per 4 bits.
// The single fp32 add here IS the reference's split-K fold (same rounding).
// ---------------------------------------------------------------------------
__global__ void __launch_bounds__(256) encode_kernel(
    const float* __restrict__ y0, const float* __restrict__ y1,
    float4* __restrict__ out, int n4)
{
    int i = blockIdx.x * blockDim.x + threadIdx.x;
    if (i >= n4) return;
    int e = i >> 3;
    int g = i & 7;
    unsigned bits = __float_as_uint(__ldg(&y0[e]) + __ldg(&y1[e]));
    int sh = 31 - g * 4;
    float4 o;
    o.x = (float)((bits >> sh)       & 1u);
    o.y = (float)((bits >> (sh - 1)) & 1u);
    o.z = (float)((bits >> (sh - 2)) & 1u);
    o.w = (float)((bits >> (sh - 3)) & 1u);
    __stcs(&out[i], o);
}

// ---------------------------------------------------------------------------
extern "C" void kernel_launch(void* const* d_in, const int* in_sizes, int n_in,
                              void* d_out, int out_size)
{
    const float4* x = (const float4*)d_in[0];   // [8,256,1024,8]
    const float4* w = (const float4*)d_in[1];   // [1024,1024,8]

    float* xf; cudaGetSymbolAddress((void**)&xf, g_xf);
    float* wf; cudaGetSymbolAddress((void**)&wf, g_wf);
    float* y0; cudaGetSymbolAddress((void**)&y0, g_y0);
    float* y1; cudaGetSymbolAddress((void**)&y1, g_y1);

    dim3 dgx(K_DIM / 32, M_DIM / 32);   // (32, 64)
    decode_t_kernel<<<dgx, 256>>>(x, xf, M_DIM);
    dim3 dgw(K_DIM / 32, N_DIM / 32);   // (32, 32)
    decode_t_kernel<<<dgw, 256>>>(w, wf, N_DIM);

    dim3 ggrid(N_DIM / BN, M_DIM / BM, 2);   // (8, 16, 2) = 256 CTAs
    gemm_kernel<<<ggrid, 256>>>();

    const int n4 = M_DIM * N_DIM * 8;
    encode_kernel<<<(n4 + 255) / 256, 256>>>(y0, y1, (float4*)d_out, n4);
}